// round 16
// baseline (speedup 1.0000x reference)
#include <cuda_runtime.h>
#include <cuda_fp16.h>
#include <cstdint>

// Problem-shape capacities (fixed by the dataset: N=100000, E=3200000)
#define NCAP 100000
#define ECAP 3200000
#define SCANB 512                            // level-1 scan block size
#define NBMAX ((NCAP + SCANB - 1) / SCANB)   // 196 <= 256

// Static device scratch. Zero-filled at module load; kernels restore "zero"
// invariants after use so every execution sees identical initial state.
__device__ unsigned long long g_degcnt[NCAP];  // hi24: count, lo40: sum(w)*2^24
__device__ float  g_dinv  [NCAP];
__device__ int    g_start [NCAP + 1];   // CSR row starts (+ total at [N])
__device__ int    g_bsum  [NBMAX];      // scan block sums
__device__ int    g_rank  [ECAP];       // per-edge rank within dst bucket
__device__ float2 g_csr   [ECAP];       // dst-sorted: {src bits, w*dinv[src]}
__device__ int4   g_hs1h  [NCAP * 4];   // h1 = x@W1, fp16 (32 halves = 64B/row)
__device__ int4   g_z1h   [NCAP * 4];   // relu layer-1 output, fp16 (64B/row)
__device__ int4   g_hs2h  [NCAP * 2];   // h2 = z1@W2, fp16 (16 halves = 32B/row)

// ---------------------------------------------------------------------------
// histogram: one packed u64 atomic gives count, weighted degree, AND the
// edge's rank within its dst bucket (returned old value).
__global__ void k_hist(const int* __restrict__ ei,
                       const float* __restrict__ ew, int E) {
    int e = blockIdx.x * blockDim.x + threadIdx.x;
    if (e >= E) return;
    int dst = __ldg(ei + E + e);
    float w = __ldg(ew + e);
    unsigned long long enc =
        (1ull << 40) | (unsigned long long)(unsigned)(w * 16777216.0f + 0.5f);
    unsigned long long old = atomicAdd(&g_degcnt[dst], enc);
    g_rank[e] = (int)(old >> 40);
}

// scan level 1: per-block (512) exclusive-scan of counts via warp shuffles.
// Also computes dinv and resets degcnt (u64 already in registers).
__global__ void k_scan1(int N) {
    __shared__ int ws[16];
    int tid  = threadIdx.x;
    int lane = tid & 31, wid = tid >> 5;
    int i = blockIdx.x * SCANB + tid;
    unsigned long long dc = (i < N) ? g_degcnt[i] : 0ull;
    int v = (int)(dc >> 40);
    int orig = v;
#pragma unroll
    for (int off = 1; off < 32; off <<= 1) {
        int t = __shfl_up_sync(0xffffffffu, v, off);
        if (lane >= off) v += t;
    }
    if (lane == 31) ws[wid] = v;
    __syncthreads();
    if (wid == 0) {
        int wv = (lane < 16) ? ws[lane] : 0;
#pragma unroll
        for (int off = 1; off < 16; off <<= 1) {
            int t = __shfl_up_sync(0xffffffffu, wv, off);
            if (lane >= off) wv += t;
        }
        if (lane < 16) ws[lane] = wv;
    }
    __syncthreads();
    int vinc = v + ((wid > 0) ? ws[wid - 1] : 0);
    if (i < N) {
        g_start[i] = vinc - orig;                 // exclusive partial
        g_degcnt[i] = 0ull;                       // restore invariant
        float deg = 1.0f + (float)(dc & 0xFFFFFFFFFFull) * (1.0f / 16777216.0f);
        g_dinv[i] = rsqrtf(deg);
    }
    if (tid == SCANB - 1) g_bsum[blockIdx.x] = vinc;
}

// scan level 2+3: each block shuffle-scans the <=256 block sums, then
// finalizes starts for 2 nodes per thread. Touches ONLY g_start.
__global__ void k_scan23(int N, int NB, int E) {
    __shared__ int ws[8];
    __shared__ int sx[256];
    int tid  = threadIdx.x;
    int lane = tid & 31, wid = tid >> 5;
    int v = (tid < NB) ? g_bsum[tid] : 0;
    int orig = v;
#pragma unroll
    for (int off = 1; off < 32; off <<= 1) {
        int t = __shfl_up_sync(0xffffffffu, v, off);
        if (lane >= off) v += t;
    }
    if (lane == 31) ws[wid] = v;
    __syncthreads();
    if (wid == 0) {
        int wv = (lane < 8) ? ws[lane] : 0;
#pragma unroll
        for (int off = 1; off < 8; off <<= 1) {
            int t = __shfl_up_sync(0xffffffffu, wv, off);
            if (lane >= off) wv += t;
        }
        if (lane < 8) ws[lane] = wv;
    }
    __syncthreads();
    sx[tid] = v + ((wid > 0) ? ws[wid - 1] : 0) - orig;  // exclusive
    __syncthreads();

    if (blockIdx.x == 0 && tid == 0) g_start[N] = E;
#pragma unroll
    for (int half = 0; half < 2; half++) {
        int i = blockIdx.x * 512 + half * 256 + tid;
        if (i < N) g_start[i] += sx[i / SCANB];
    }
}

// scatter edges into dst-sorted CSR, NO atomics: p = start[dst] + rank[e].
__global__ void k_scatter(const int* __restrict__ ei,
                          const float* __restrict__ ew, int E) {
    int e = blockIdx.x * blockDim.x + threadIdx.x;
    if (e >= E) return;
    int src = __ldg(ei + e);
    int dst = __ldg(ei + E + e);
    float w = __ldg(ew + e) * __ldg(g_dinv + src);
    int p = __ldg(g_start + dst) + g_rank[e];
    g_csr[p] = make_float2(__int_as_float(src), w);
}

// ---------------------------------------------------------------------------
// Register-tiled GEMM1 (TM=4, BM=128), fp16 epilogue store -> g_hs1h.
__global__ void __launch_bounds__(256)
k_gemm1(const float* __restrict__ X, const float* __restrict__ W, int N) {
    constexpr int FIN = 128, FOUT = 32;
    constexpr int NCT = FOUT / 4;       // 8
    constexpr int TM  = 4;
    constexpr int BM  = 32 * TM;        // 128 rows/block

    __shared__ float sW[FIN * FOUT];
    for (int i = threadIdx.x; i < FIN * FOUT / 4; i += 256)
        reinterpret_cast<float4*>(sW)[i] =
            __ldg(reinterpret_cast<const float4*>(W) + i);
    __syncthreads();

    const int ci = threadIdx.x % NCT;
    const int ri = threadIdx.x / NCT;
    const int r0 = blockIdx.x * BM + ri * TM;
    const bool full = (r0 + TM <= N);

    float acc[TM][4];
#pragma unroll
    for (int t = 0; t < TM; t++)
#pragma unroll
        for (int j = 0; j < 4; j++) acc[t][j] = 0.0f;

#pragma unroll 4
    for (int k4 = 0; k4 < FIN / 4; k4++) {
        float xr[TM][4];
#pragma unroll
        for (int t = 0; t < TM; t++) {
            float4 v = make_float4(0.f, 0.f, 0.f, 0.f);
            int r = r0 + t;
            if (full || r < N)
                v = __ldg(reinterpret_cast<const float4*>(X + (size_t)r * FIN) + k4);
            xr[t][0] = v.x; xr[t][1] = v.y; xr[t][2] = v.z; xr[t][3] = v.w;
        }
#pragma unroll
        for (int kk = 0; kk < 4; kk++) {
            float4 wv = *reinterpret_cast<const float4*>(
                &sW[(k4 * 4 + kk) * FOUT + ci * 4]);
#pragma unroll
            for (int t = 0; t < TM; t++) {
                float xs = xr[t][kk];
                acc[t][0] += xs * wv.x;
                acc[t][1] += xs * wv.y;
                acc[t][2] += xs * wv.z;
                acc[t][3] += xs * wv.w;
            }
        }
    }

    uint2* HS = reinterpret_cast<uint2*>(g_hs1h);
#pragma unroll
    for (int t = 0; t < TM; t++) {
        int r = r0 + t;
        if (full || r < N) {
            __half2 lo = __float22half2_rn(make_float2(acc[t][0], acc[t][1]));
            __half2 hi = __float22half2_rn(make_float2(acc[t][2], acc[t][3]));
            uint2 pk;
            pk.x = *reinterpret_cast<unsigned*>(&lo);
            pk.y = *reinterpret_cast<unsigned*>(&hi);
            HS[(size_t)r * NCT + ci] = pk;
        }
    }
}

// ---------------------------------------------------------------------------
// GEMM2 (32 -> 16), reads z1 in fp16, fp32 math, fp16 store -> g_hs2h.
__global__ void __launch_bounds__(128)
k_gemm2(const float* __restrict__ W, int N) {
    constexpr int FIN = 32, FOUT = 16;
    constexpr int NCT = FOUT / 4;       // 4
    constexpr int TM  = 4;
    constexpr int BM  = 32 * TM;        // 128 rows/block

    __shared__ float sW[FIN * FOUT];
    for (int i = threadIdx.x; i < FIN * FOUT / 4; i += 128)
        reinterpret_cast<float4*>(sW)[i] =
            __ldg(reinterpret_cast<const float4*>(W) + i);
    __syncthreads();

    const int ci = threadIdx.x % NCT;
    const int ri = threadIdx.x / NCT;
    const int r0 = blockIdx.x * BM + ri * TM;
    const bool full = (r0 + TM <= N);

    float acc[TM][4];
#pragma unroll
    for (int t = 0; t < TM; t++)
#pragma unroll
        for (int j = 0; j < 4; j++) acc[t][j] = 0.0f;

    const uint2* Z = reinterpret_cast<const uint2*>(g_z1h);
#pragma unroll
    for (int k4 = 0; k4 < FIN / 4; k4++) {
        float xr[TM][4];
#pragma unroll
        for (int t = 0; t < TM; t++) {
            int r = r0 + t;
            xr[t][0] = xr[t][1] = xr[t][2] = xr[t][3] = 0.0f;
            if (full || r < N) {
                uint2 pv = __ldg(Z + (size_t)r * 8 + k4);   // 4 halves = 8B
                float2 a = __half22float2(*reinterpret_cast<const __half2*>(&pv.x));
                float2 b = __half22float2(*reinterpret_cast<const __half2*>(&pv.y));
                xr[t][0] = a.x; xr[t][1] = a.y; xr[t][2] = b.x; xr[t][3] = b.y;
            }
        }
#pragma unroll
        for (int kk = 0; kk < 4; kk++) {
            float4 wv = *reinterpret_cast<const float4*>(
                &sW[(k4 * 4 + kk) * FOUT + ci * 4]);
#pragma unroll
            for (int t = 0; t < TM; t++) {
                float xs = xr[t][kk];
                acc[t][0] += xs * wv.x;
                acc[t][1] += xs * wv.y;
                acc[t][2] += xs * wv.z;
                acc[t][3] += xs * wv.w;
            }
        }
    }

    uint2* HS = reinterpret_cast<uint2*>(g_hs2h);
#pragma unroll
    for (int t = 0; t < TM; t++) {
        int r = r0 + t;
        if (full || r < N) {
            __half2 lo = __float22half2_rn(make_float2(acc[t][0], acc[t][1]));
            __half2 hi = __float22half2_rn(make_float2(acc[t][2], acc[t][3]));
            uint2 pk;
            pk.x = *reinterpret_cast<unsigned*>(&lo);
            pk.y = *reinterpret_cast<unsigned*>(&hi);
            HS[(size_t)r * NCT + ci] = pk;
        }
    }
}

// helper: int4 of 8 halves -> 8 floats
__device__ __forceinline__ void unpack8(const int4& p, float* f) {
    __half2 h0 = *reinterpret_cast<const __half2*>(&p.x);
    __half2 h1 = *reinterpret_cast<const __half2*>(&p.y);
    __half2 h2 = *reinterpret_cast<const __half2*>(&p.z);
    __half2 h3 = *reinterpret_cast<const __half2*>(&p.w);
    float2 a = __half22float2(h0), b = __half22float2(h1);
    float2 c = __half22float2(h2), d = __half22float2(h3);
    f[0] = a.x; f[1] = a.y; f[2] = b.x; f[3] = b.y;
    f[4] = c.x; f[5] = c.y; f[6] = d.x; f[7] = d.y;
}

// ---------------------------------------------------------------------------
// CSR aggregation layer 1: warp per node, 8 edge-groups x 4 chunk-threads,
// 2x-unrolled so two csr loads and two hs gathers are in flight per round.
// z1 = relu(s*(sum_e w'*h1[src] + s*h1[node]) + b1), stored fp16.
__global__ void k_agg1(const float* __restrict__ b1, int N) {
    int warp = (blockIdx.x * blockDim.x + threadIdx.x) >> 5;
    if (warp >= N) return;
    int lane = threadIdx.x & 31;
    int c  = lane & 3;        // feature chunk: 8 halves (16B)
    int eg = lane >> 2;       // edge group 0..7

    int start = __ldg(g_start + warp);
    int cnt   = __ldg(g_start + warp + 1) - start;

    float acc[8];
#pragma unroll
    for (int q = 0; q < 8; q++) acc[q] = 0.0f;

    for (int k = eg; k < cnt; k += 16) {
        float2 e0 = __ldg(g_csr + start + k);
        int k1 = k + 8;
        float2 e1 = (k1 < cnt) ? __ldg(g_csr + start + k1)
                               : make_float2(e0.x, 0.0f);
        int s0 = __float_as_int(e0.x);
        int s1 = __float_as_int(e1.x);
        int4 p0 = __ldg(g_hs1h + (size_t)s0 * 4 + c);
        int4 p1 = __ldg(g_hs1h + (size_t)s1 * 4 + c);
        float f0[8], f1[8];
        unpack8(p0, f0); unpack8(p1, f1);
#pragma unroll
        for (int q = 0; q < 8; q++)
            acc[q] += e0.y * f0[q] + e1.y * f1[q];
    }
#pragma unroll
    for (int m = 4; m <= 16; m <<= 1)
#pragma unroll
        for (int q = 0; q < 8; q++)
            acc[q] += __shfl_xor_sync(0xffffffffu, acc[q], m);

    if (eg == 0) {
        float s = g_dinv[warp];
        int4 p = __ldg(g_hs1h + (size_t)warp * 4 + c);
        float h[8]; unpack8(p, h);
        float4 b0 = __ldg(reinterpret_cast<const float4*>(b1) + c * 2);
        float4 b1v = __ldg(reinterpret_cast<const float4*>(b1) + c * 2 + 1);
        float bb[8] = {b0.x, b0.y, b0.z, b0.w, b1v.x, b1v.y, b1v.z, b1v.w};
        float z[8];
#pragma unroll
        for (int q = 0; q < 8; q++)
            z[q] = fmaxf(s * (acc[q] + s * h[q]) + bb[q], 0.0f);
        // store fp16: 8 floats -> 4 half2 = int4
        __half2 q0 = __float22half2_rn(make_float2(z[0], z[1]));
        __half2 q1 = __float22half2_rn(make_float2(z[2], z[3]));
        __half2 q2 = __float22half2_rn(make_float2(z[4], z[5]));
        __half2 q3 = __float22half2_rn(make_float2(z[6], z[7]));
        int4 pk;
        pk.x = *reinterpret_cast<int*>(&q0);
        pk.y = *reinterpret_cast<int*>(&q1);
        pk.z = *reinterpret_cast<int*>(&q2);
        pk.w = *reinterpret_cast<int*>(&q3);
        g_z1h[(size_t)warp * 4 + c] = pk;
    }
}

// ---------------------------------------------------------------------------
// CSR aggregation layer 2 + fused final linear (16 -> 3), 2x-unrolled.
// 16 edge-groups x 2 chunk-threads (8 halves each).
__global__ void k_agg2_out(const float* __restrict__ b2,
                           const float* __restrict__ Wout,
                           const float* __restrict__ bout,
                           float* __restrict__ out, int N) {
    __shared__ float sW[48];
    __shared__ float sb[3];
    if (threadIdx.x < 48) sW[threadIdx.x] = __ldg(Wout + threadIdx.x);
    if (threadIdx.x < 3)  sb[threadIdx.x] = __ldg(bout + threadIdx.x);
    __syncthreads();

    int warp = (blockIdx.x * blockDim.x + threadIdx.x) >> 5;
    if (warp >= N) return;
    int lane = threadIdx.x & 31;
    int c  = lane & 1;        // feature chunk: 8 halves (16B), 2 chunks = 16
    int eg = lane >> 1;       // edge group 0..15

    int start = __ldg(g_start + warp);
    int cnt   = __ldg(g_start + warp + 1) - start;

    float acc[8];
#pragma unroll
    for (int q = 0; q < 8; q++) acc[q] = 0.0f;

    for (int k = eg; k < cnt; k += 32) {
        float2 e0 = __ldg(g_csr + start + k);
        int k1 = k + 16;
        float2 e1 = (k1 < cnt) ? __ldg(g_csr + start + k1)
                               : make_float2(e0.x, 0.0f);
        int s0 = __float_as_int(e0.x);
        int s1 = __float_as_int(e1.x);
        int4 p0 = __ldg(g_hs2h + (size_t)s0 * 2 + c);
        int4 p1 = __ldg(g_hs2h + (size_t)s1 * 2 + c);
        float f0[8], f1[8];
        unpack8(p0, f0); unpack8(p1, f1);
#pragma unroll
        for (int q = 0; q < 8; q++)
            acc[q] += e0.y * f0[q] + e1.y * f1[q];
    }
#pragma unroll
    for (int m = 2; m <= 16; m <<= 1)
#pragma unroll
        for (int q = 0; q < 8; q++)
            acc[q] += __shfl_xor_sync(0xffffffffu, acc[q], m);

    // lanes 0..1 hold the 2 chunks
    float s = g_dinv[warp];
    int4 p = __ldg(g_hs2h + (size_t)warp * 2 + c);
    float h[8]; unpack8(p, h);
    float4 b0 = __ldg(reinterpret_cast<const float4*>(b2) + c * 2);
    float4 b1v = __ldg(reinterpret_cast<const float4*>(b2) + c * 2 + 1);
    float bb[8] = {b0.x, b0.y, b0.z, b0.w, b1v.x, b1v.y, b1v.z, b1v.w};

    float a0 = 0.f, a1 = 0.f, a2 = 0.f;
#pragma unroll
    for (int q = 0; q < 8; q++) {
        float z = fmaxf(s * (acc[q] + s * h[q]) + bb[q], 0.0f);
        int kk = c * 8 + q;
        a0 += z * sW[kk * 3 + 0];
        a1 += z * sW[kk * 3 + 1];
        a2 += z * sW[kk * 3 + 2];
    }
    a0 += __shfl_xor_sync(0xffffffffu, a0, 1);
    a1 += __shfl_xor_sync(0xffffffffu, a1, 1);
    a2 += __shfl_xor_sync(0xffffffffu, a2, 1);
    if (lane == 0) {
        float* o = out + (size_t)warp * 3;
        o[0] = a0 + sb[0]; o[1] = a1 + sb[1]; o[2] = a2 + sb[2];
    }
}

// ---------------------------------------------------------------------------
extern "C" void kernel_launch(void* const* d_in, const int* in_sizes, int n_in,
                              void* d_out, int out_size) {
    const float* x    = (const float*)d_in[0];
    const int*   ei   = (const int*)d_in[1];     // int32 [2, E]
    const float* ew   = (const float*)d_in[2];
    const float* W1   = (const float*)d_in[3];
    const float* b1   = (const float*)d_in[4];
    const float* W2   = (const float*)d_in[5];
    const float* b2   = (const float*)d_in[6];
    const float* Wout = (const float*)d_in[7];
    const float* bout = (const float*)d_in[8];
    float*       out  = (float*)d_out;

    const int N  = in_sizes[0] / 128;
    const int E  = in_sizes[2];
    const int NB = (N + SCANB - 1) / SCANB;

    const int B = 256;
    auto blocks = [B](long long n) { return (unsigned)((n + B - 1) / B); };

    static cudaStream_t s_side = nullptr;
    static cudaEvent_t  s_ev0 = nullptr, s_ev1 = nullptr;
    if (s_side == nullptr) {
        cudaStreamCreateWithFlags(&s_side, cudaStreamNonBlocking);
        cudaEventCreateWithFlags(&s_ev0, cudaEventDisableTiming);
        cudaEventCreateWithFlags(&s_ev1, cudaEventDisableTiming);
    }

    // Fork: gemm1 (independent of the CSR chain) on the side stream.
    cudaEventRecord(s_ev0, 0);
    cudaStreamWaitEvent(s_side, s_ev0, 0);
    k_gemm1<<<(N + 127) / 128, 256, 0, s_side>>>(x, W1, N);
    cudaEventRecord(s_ev1, s_side);

    // Main stream: CSR build (+ dinv), overlapped with gemm1.
    k_hist   <<<blocks(E), B>>>(ei, ew, E);
    k_scan1  <<<NB, SCANB>>>(N);
    k_scan23 <<<(unsigned)((N + 511) / 512), 256>>>(N, NB, E);
    k_scatter<<<blocks(E), B>>>(ei, ew, E);

    // Join, then the serial tail.
    cudaStreamWaitEvent(0, s_ev1, 0);
    k_agg1<<<blocks((long long)N * 32), B>>>(b1, N);
    k_gemm2<<<(N + 127) / 128, 128>>>(W2, N);
    k_agg2_out<<<blocks((long long)N * 32), B>>>(b2, Wout, bout, out, N);
}

// round 17
// speedup vs baseline: 1.4913x; 1.4913x over previous
#include <cuda_runtime.h>
#include <cuda_fp16.h>
#include <cstdint>

// Problem-shape capacities (fixed by the dataset: N=100000, E=3200000)
#define NCAP 100000
#define ECAP 3200000
#define SCANB 512                            // level-1 scan block size
#define NBMAX ((NCAP + SCANB - 1) / SCANB)   // 196 <= 256

// Static device scratch. Zero-filled at module load; kernels restore "zero"
// invariants after use so every execution sees identical initial state.
__device__ unsigned long long g_degcnt[NCAP];  // hi24: count, lo40: sum(w)*2^24
__device__ float  g_dinv  [NCAP];
__device__ int    g_start [NCAP + 1];   // CSR row starts (+ total at [N])
__device__ int    g_bsum  [NBMAX];      // scan block sums
__device__ int    g_rank  [ECAP];       // per-edge rank within dst bucket
__device__ float2 g_csr   [ECAP];       // dst-sorted: {src bits, w*dinv[src]}
__device__ int4   g_hs1h  [NCAP * 4];   // h1 = x@W1, fp16 (32 halves = 64B/row)
__device__ int4   g_z1h   [NCAP * 4];   // relu layer-1 output, fp16 (64B/row)
__device__ int4   g_hs2h  [NCAP * 2];   // h2 = z1@W2, fp16 (16 halves = 32B/row)

// ---------------------------------------------------------------------------
// histogram: one packed u64 atomic gives count, weighted degree, AND the
// edge's rank within its dst bucket (returned old value).
__global__ void k_hist(const int* __restrict__ ei,
                       const float* __restrict__ ew, int E) {
    int e = blockIdx.x * blockDim.x + threadIdx.x;
    if (e >= E) return;
    int dst = __ldg(ei + E + e);
    float w = __ldg(ew + e);
    unsigned long long enc =
        (1ull << 40) | (unsigned long long)(unsigned)(w * 16777216.0f + 0.5f);
    unsigned long long old = atomicAdd(&g_degcnt[dst], enc);
    g_rank[e] = (int)(old >> 40);
}

// scan level 1: per-block (512) exclusive-scan of counts via warp shuffles.
// Also computes dinv and resets degcnt (u64 already in registers).
__global__ void k_scan1(int N) {
    __shared__ int ws[16];
    int tid  = threadIdx.x;
    int lane = tid & 31, wid = tid >> 5;
    int i = blockIdx.x * SCANB + tid;
    unsigned long long dc = (i < N) ? g_degcnt[i] : 0ull;
    int v = (int)(dc >> 40);
    int orig = v;
#pragma unroll
    for (int off = 1; off < 32; off <<= 1) {
        int t = __shfl_up_sync(0xffffffffu, v, off);
        if (lane >= off) v += t;
    }
    if (lane == 31) ws[wid] = v;
    __syncthreads();
    if (wid == 0) {
        int wv = (lane < 16) ? ws[lane] : 0;
#pragma unroll
        for (int off = 1; off < 16; off <<= 1) {
            int t = __shfl_up_sync(0xffffffffu, wv, off);
            if (lane >= off) wv += t;
        }
        if (lane < 16) ws[lane] = wv;
    }
    __syncthreads();
    int vinc = v + ((wid > 0) ? ws[wid - 1] : 0);
    if (i < N) {
        g_start[i] = vinc - orig;                 // exclusive partial
        g_degcnt[i] = 0ull;                       // restore invariant
        float deg = 1.0f + (float)(dc & 0xFFFFFFFFFFull) * (1.0f / 16777216.0f);
        g_dinv[i] = rsqrtf(deg);
    }
    if (tid == SCANB - 1) g_bsum[blockIdx.x] = vinc;
}

// scan level 2+3: each block shuffle-scans the <=256 block sums, then
// finalizes starts for 2 nodes per thread. Touches ONLY g_start.
__global__ void k_scan23(int N, int NB, int E) {
    __shared__ int ws[8];
    __shared__ int sx[256];
    int tid  = threadIdx.x;
    int lane = tid & 31, wid = tid >> 5;
    int v = (tid < NB) ? g_bsum[tid] : 0;
    int orig = v;
#pragma unroll
    for (int off = 1; off < 32; off <<= 1) {
        int t = __shfl_up_sync(0xffffffffu, v, off);
        if (lane >= off) v += t;
    }
    if (lane == 31) ws[wid] = v;
    __syncthreads();
    if (wid == 0) {
        int wv = (lane < 8) ? ws[lane] : 0;
#pragma unroll
        for (int off = 1; off < 8; off <<= 1) {
            int t = __shfl_up_sync(0xffffffffu, wv, off);
            if (lane >= off) wv += t;
        }
        if (lane < 8) ws[lane] = wv;
    }
    __syncthreads();
    sx[tid] = v + ((wid > 0) ? ws[wid - 1] : 0) - orig;  // exclusive
    __syncthreads();

    if (blockIdx.x == 0 && tid == 0) g_start[N] = E;
#pragma unroll
    for (int half = 0; half < 2; half++) {
        int i = blockIdx.x * 512 + half * 256 + tid;
        if (i < N) g_start[i] += sx[i / SCANB];
    }
}

// scatter edges into dst-sorted CSR, NO atomics: p = start[dst] + rank[e].
__global__ void k_scatter(const int* __restrict__ ei,
                          const float* __restrict__ ew, int E) {
    int e = blockIdx.x * blockDim.x + threadIdx.x;
    if (e >= E) return;
    int src = __ldg(ei + e);
    int dst = __ldg(ei + E + e);
    float w = __ldg(ew + e) * __ldg(g_dinv + src);
    int p = __ldg(g_start + dst) + g_rank[e];
    g_csr[p] = make_float2(__int_as_float(src), w);
}

// ---------------------------------------------------------------------------
// Register-tiled GEMM1 (TM=4, BM=128), fp16 epilogue store -> g_hs1h.
__global__ void __launch_bounds__(256)
k_gemm1(const float* __restrict__ X, const float* __restrict__ W, int N) {
    constexpr int FIN = 128, FOUT = 32;
    constexpr int NCT = FOUT / 4;       // 8
    constexpr int TM  = 4;
    constexpr int BM  = 32 * TM;        // 128 rows/block

    __shared__ float sW[FIN * FOUT];
    for (int i = threadIdx.x; i < FIN * FOUT / 4; i += 256)
        reinterpret_cast<float4*>(sW)[i] =
            __ldg(reinterpret_cast<const float4*>(W) + i);
    __syncthreads();

    const int ci = threadIdx.x % NCT;
    const int ri = threadIdx.x / NCT;
    const int r0 = blockIdx.x * BM + ri * TM;
    const bool full = (r0 + TM <= N);

    float acc[TM][4];
#pragma unroll
    for (int t = 0; t < TM; t++)
#pragma unroll
        for (int j = 0; j < 4; j++) acc[t][j] = 0.0f;

#pragma unroll 4
    for (int k4 = 0; k4 < FIN / 4; k4++) {
        float xr[TM][4];
#pragma unroll
        for (int t = 0; t < TM; t++) {
            float4 v = make_float4(0.f, 0.f, 0.f, 0.f);
            int r = r0 + t;
            if (full || r < N)
                v = __ldg(reinterpret_cast<const float4*>(X + (size_t)r * FIN) + k4);
            xr[t][0] = v.x; xr[t][1] = v.y; xr[t][2] = v.z; xr[t][3] = v.w;
        }
#pragma unroll
        for (int kk = 0; kk < 4; kk++) {
            float4 wv = *reinterpret_cast<const float4*>(
                &sW[(k4 * 4 + kk) * FOUT + ci * 4]);
#pragma unroll
            for (int t = 0; t < TM; t++) {
                float xs = xr[t][kk];
                acc[t][0] += xs * wv.x;
                acc[t][1] += xs * wv.y;
                acc[t][2] += xs * wv.z;
                acc[t][3] += xs * wv.w;
            }
        }
    }

    uint2* HS = reinterpret_cast<uint2*>(g_hs1h);
#pragma unroll
    for (int t = 0; t < TM; t++) {
        int r = r0 + t;
        if (full || r < N) {
            __half2 lo = __float22half2_rn(make_float2(acc[t][0], acc[t][1]));
            __half2 hi = __float22half2_rn(make_float2(acc[t][2], acc[t][3]));
            uint2 pk;
            pk.x = *reinterpret_cast<unsigned*>(&lo);
            pk.y = *reinterpret_cast<unsigned*>(&hi);
            HS[(size_t)r * NCT + ci] = pk;
        }
    }
}

// ---------------------------------------------------------------------------
// GEMM2 (32 -> 16), reads z1 in fp16, fp32 math, fp16 store -> g_hs2h.
__global__ void __launch_bounds__(128)
k_gemm2(const float* __restrict__ W, int N) {
    constexpr int FIN = 32, FOUT = 16;
    constexpr int NCT = FOUT / 4;       // 4
    constexpr int TM  = 4;
    constexpr int BM  = 32 * TM;        // 128 rows/block

    __shared__ float sW[FIN * FOUT];
    for (int i = threadIdx.x; i < FIN * FOUT / 4; i += 128)
        reinterpret_cast<float4*>(sW)[i] =
            __ldg(reinterpret_cast<const float4*>(W) + i);
    __syncthreads();

    const int ci = threadIdx.x % NCT;
    const int ri = threadIdx.x / NCT;
    const int r0 = blockIdx.x * BM + ri * TM;
    const bool full = (r0 + TM <= N);

    float acc[TM][4];
#pragma unroll
    for (int t = 0; t < TM; t++)
#pragma unroll
        for (int j = 0; j < 4; j++) acc[t][j] = 0.0f;

    const uint2* Z = reinterpret_cast<const uint2*>(g_z1h);
#pragma unroll
    for (int k4 = 0; k4 < FIN / 4; k4++) {
        float xr[TM][4];
#pragma unroll
        for (int t = 0; t < TM; t++) {
            int r = r0 + t;
            xr[t][0] = xr[t][1] = xr[t][2] = xr[t][3] = 0.0f;
            if (full || r < N) {
                uint2 pv = __ldg(Z + (size_t)r * 8 + k4);   // 4 halves = 8B
                float2 a = __half22float2(*reinterpret_cast<const __half2*>(&pv.x));
                float2 b = __half22float2(*reinterpret_cast<const __half2*>(&pv.y));
                xr[t][0] = a.x; xr[t][1] = a.y; xr[t][2] = b.x; xr[t][3] = b.y;
            }
        }
#pragma unroll
        for (int kk = 0; kk < 4; kk++) {
            float4 wv = *reinterpret_cast<const float4*>(
                &sW[(k4 * 4 + kk) * FOUT + ci * 4]);
#pragma unroll
            for (int t = 0; t < TM; t++) {
                float xs = xr[t][kk];
                acc[t][0] += xs * wv.x;
                acc[t][1] += xs * wv.y;
                acc[t][2] += xs * wv.z;
                acc[t][3] += xs * wv.w;
            }
        }
    }

    uint2* HS = reinterpret_cast<uint2*>(g_hs2h);
#pragma unroll
    for (int t = 0; t < TM; t++) {
        int r = r0 + t;
        if (full || r < N) {
            __half2 lo = __float22half2_rn(make_float2(acc[t][0], acc[t][1]));
            __half2 hi = __float22half2_rn(make_float2(acc[t][2], acc[t][3]));
            uint2 pk;
            pk.x = *reinterpret_cast<unsigned*>(&lo);
            pk.y = *reinterpret_cast<unsigned*>(&hi);
            HS[(size_t)r * NCT + ci] = pk;
        }
    }
}

// helper: int4 of 8 halves -> 8 floats
__device__ __forceinline__ void unpack8(const int4& p, float* f) {
    __half2 h0 = *reinterpret_cast<const __half2*>(&p.x);
    __half2 h1 = *reinterpret_cast<const __half2*>(&p.y);
    __half2 h2 = *reinterpret_cast<const __half2*>(&p.z);
    __half2 h3 = *reinterpret_cast<const __half2*>(&p.w);
    float2 a = __half22float2(h0), b = __half22float2(h1);
    float2 c = __half22float2(h2), d = __half22float2(h3);
    f[0] = a.x; f[1] = a.y; f[2] = b.x; f[3] = b.y;
    f[4] = c.x; f[5] = c.y; f[6] = d.x; f[7] = d.y;
}

// ---------------------------------------------------------------------------
// CSR aggregation layer 1: warp per node, 8 edge-groups x 4 chunk-threads.
// Simple (non-unrolled) loop — the R16 unroll regressed badly.
// z1 = relu(s*(sum_e w'*h1[src] + s*h1[node]) + b1), stored fp16.
__global__ void k_agg1(const float* __restrict__ b1, int N) {
    int warp = (blockIdx.x * blockDim.x + threadIdx.x) >> 5;
    if (warp >= N) return;
    int lane = threadIdx.x & 31;
    int c  = lane & 3;        // feature chunk: 8 halves (16B)
    int eg = lane >> 2;       // edge group 0..7

    int start = __ldg(g_start + warp);
    int cnt   = __ldg(g_start + warp + 1) - start;

    float acc[8];
#pragma unroll
    for (int q = 0; q < 8; q++) acc[q] = 0.0f;

    for (int k = eg; k < cnt; k += 8) {
        float2 ed = __ldg(g_csr + start + k);
        int   src = __float_as_int(ed.x);
        float w   = ed.y;
        int4 p = __ldg(g_hs1h + (size_t)src * 4 + c);
        float f[8]; unpack8(p, f);
#pragma unroll
        for (int q = 0; q < 8; q++) acc[q] += w * f[q];
    }
#pragma unroll
    for (int m = 4; m <= 16; m <<= 1)
#pragma unroll
        for (int q = 0; q < 8; q++)
            acc[q] += __shfl_xor_sync(0xffffffffu, acc[q], m);

    if (eg == 0) {
        float s = g_dinv[warp];
        int4 p = __ldg(g_hs1h + (size_t)warp * 4 + c);
        float h[8]; unpack8(p, h);
        float4 b0 = __ldg(reinterpret_cast<const float4*>(b1) + c * 2);
        float4 b1v = __ldg(reinterpret_cast<const float4*>(b1) + c * 2 + 1);
        float bb[8] = {b0.x, b0.y, b0.z, b0.w, b1v.x, b1v.y, b1v.z, b1v.w};
        float z[8];
#pragma unroll
        for (int q = 0; q < 8; q++)
            z[q] = fmaxf(s * (acc[q] + s * h[q]) + bb[q], 0.0f);
        // store fp16: 8 floats -> 4 half2 = int4
        __half2 q0 = __float22half2_rn(make_float2(z[0], z[1]));
        __half2 q1 = __float22half2_rn(make_float2(z[2], z[3]));
        __half2 q2 = __float22half2_rn(make_float2(z[4], z[5]));
        __half2 q3 = __float22half2_rn(make_float2(z[6], z[7]));
        int4 pk;
        pk.x = *reinterpret_cast<int*>(&q0);
        pk.y = *reinterpret_cast<int*>(&q1);
        pk.z = *reinterpret_cast<int*>(&q2);
        pk.w = *reinterpret_cast<int*>(&q3);
        g_z1h[(size_t)warp * 4 + c] = pk;
    }
}

// ---------------------------------------------------------------------------
// CSR aggregation layer 2 + fused final linear (16 -> 3).
// 16 edge-groups x 2 chunk-threads (8 halves each); simple loop.
__global__ void k_agg2_out(const float* __restrict__ b2,
                           const float* __restrict__ Wout,
                           const float* __restrict__ bout,
                           float* __restrict__ out, int N) {
    __shared__ float sW[48];
    __shared__ float sb[3];
    if (threadIdx.x < 48) sW[threadIdx.x] = __ldg(Wout + threadIdx.x);
    if (threadIdx.x < 3)  sb[threadIdx.x] = __ldg(bout + threadIdx.x);
    __syncthreads();

    int warp = (blockIdx.x * blockDim.x + threadIdx.x) >> 5;
    if (warp >= N) return;
    int lane = threadIdx.x & 31;
    int c  = lane & 1;        // feature chunk: 8 halves (16B), 2 chunks = 16
    int eg = lane >> 1;       // edge group 0..15

    int start = __ldg(g_start + warp);
    int cnt   = __ldg(g_start + warp + 1) - start;

    float acc[8];
#pragma unroll
    for (int q = 0; q < 8; q++) acc[q] = 0.0f;

    for (int k = eg; k < cnt; k += 16) {
        float2 ed = __ldg(g_csr + start + k);
        int   src = __float_as_int(ed.x);
        float w   = ed.y;
        int4 p = __ldg(g_hs2h + (size_t)src * 2 + c);
        float f[8]; unpack8(p, f);
#pragma unroll
        for (int q = 0; q < 8; q++) acc[q] += w * f[q];
    }
#pragma unroll
    for (int m = 2; m <= 16; m <<= 1)
#pragma unroll
        for (int q = 0; q < 8; q++)
            acc[q] += __shfl_xor_sync(0xffffffffu, acc[q], m);

    // lanes 0..1 hold the 2 chunks
    float s = g_dinv[warp];
    int4 p = __ldg(g_hs2h + (size_t)warp * 2 + c);
    float h[8]; unpack8(p, h);
    float4 b0 = __ldg(reinterpret_cast<const float4*>(b2) + c * 2);
    float4 b1v = __ldg(reinterpret_cast<const float4*>(b2) + c * 2 + 1);
    float bb[8] = {b0.x, b0.y, b0.z, b0.w, b1v.x, b1v.y, b1v.z, b1v.w};

    float a0 = 0.f, a1 = 0.f, a2 = 0.f;
#pragma unroll
    for (int q = 0; q < 8; q++) {
        float z = fmaxf(s * (acc[q] + s * h[q]) + bb[q], 0.0f);
        int kk = c * 8 + q;
        a0 += z * sW[kk * 3 + 0];
        a1 += z * sW[kk * 3 + 1];
        a2 += z * sW[kk * 3 + 2];
    }
    a0 += __shfl_xor_sync(0xffffffffu, a0, 1);
    a1 += __shfl_xor_sync(0xffffffffu, a1, 1);
    a2 += __shfl_xor_sync(0xffffffffu, a2, 1);
    if (lane == 0) {
        float* o = out + (size_t)warp * 3;
        o[0] = a0 + sb[0]; o[1] = a1 + sb[1]; o[2] = a2 + sb[2];
    }
}

// ---------------------------------------------------------------------------
extern "C" void kernel_launch(void* const* d_in, const int* in_sizes, int n_in,
                              void* d_out, int out_size) {
    const float* x    = (const float*)d_in[0];
    const int*   ei   = (const int*)d_in[1];     // int32 [2, E]
    const float* ew   = (const float*)d_in[2];
    const float* W1   = (const float*)d_in[3];
    const float* b1   = (const float*)d_in[4];
    const float* W2   = (const float*)d_in[5];
    const float* b2   = (const float*)d_in[6];
    const float* Wout = (const float*)d_in[7];
    const float* bout = (const float*)d_in[8];
    float*       out  = (float*)d_out;

    const int N  = in_sizes[0] / 128;
    const int E  = in_sizes[2];
    const int NB = (N + SCANB - 1) / SCANB;

    const int B = 256;
    auto blocks = [B](long long n) { return (unsigned)((n + B - 1) / B); };

    static cudaStream_t s_side = nullptr;
    static cudaEvent_t  s_ev0 = nullptr, s_ev1 = nullptr;
    if (s_side == nullptr) {
        cudaStreamCreateWithFlags(&s_side, cudaStreamNonBlocking);
        cudaEventCreateWithFlags(&s_ev0, cudaEventDisableTiming);
        cudaEventCreateWithFlags(&s_ev1, cudaEventDisableTiming);
    }

    // Fork: gemm1 (independent of the CSR chain) on the side stream.
    cudaEventRecord(s_ev0, 0);
    cudaStreamWaitEvent(s_side, s_ev0, 0);
    k_gemm1<<<(N + 127) / 128, 256, 0, s_side>>>(x, W1, N);
    cudaEventRecord(s_ev1, s_side);

    // Main stream: CSR build (+ dinv), overlapped with gemm1.
    k_hist   <<<blocks(E), B>>>(ei, ew, E);
    k_scan1  <<<NB, SCANB>>>(N);
    k_scan23 <<<(unsigned)((N + 511) / 512), 256>>>(N, NB, E);
    k_scatter<<<blocks(E), B>>>(ei, ew, E);

    // Join, then the serial tail.
    cudaStreamWaitEvent(0, s_ev1, 0);
    k_agg1<<<blocks((long long)N * 32), B>>>(b1, N);
    k_gemm2<<<(N + 127) / 128, 128>>>(W2, N);
    k_agg2_out<<<blocks((long long)N * 32), B>>>(b2, Wout, bout, out, N);
}